// round 12
// baseline (speedup 1.0000x reference)
#include <cuda_runtime.h>
#include <cuda_bf16.h>
#include <cstdint>

#define N_NODES 100000
#define N_EDGES 600000
#define D_IN    128
#define D_OUT   96
#define N_REL   4

#define TILE_M    64
#define N_TILES64 1563               // ceil(100000/64)

#define ROW_BYTES 272                // 128 bf16 (256B) + 16B pad -> conflict-free ldmatrix
#define A_IMG_BYTES (TILE_M * ROW_BYTES)   // 17408
#define B1_ROWS 128
#define B2_ROWS 96
#define B1_IMG_BYTES (B1_ROWS * ROW_BYTES) // 34816
#define B2_IMG_BYTES (B2_ROWS * ROW_BYTES) // 26112

// ---------------- scratch (static device globals; no allocs allowed) --------
__device__ __align__(16) float g_out1[(size_t)N_NODES * D_IN];          // 51.2 MB
__device__ int      g_cnt[N_NODES * N_REL];
__device__ int      g_cursor[N_NODES * N_REL];
__device__ int      g_base[N_NODES];
__device__ int      g_total;
__device__ uint32_t g_csr[N_EDGES];

// weight images (bf16 hi/lo, padded rows). B2 rows 96 only.
__device__ uint4 g_B1hi[5 * (B1_IMG_BYTES / 16)];
__device__ uint4 g_B1lo[5 * (B1_IMG_BYTES / 16)];
__device__ uint4 g_B2hi[5 * (B2_IMG_BYTES / 16)];
__device__ uint4 g_B2lo[5 * (B2_IMG_BYTES / 16)];

// ---------------- helpers ----------------------------------------------------
__device__ __forceinline__ uint32_t smem_u32(const void* p) {
    uint32_t a;
    asm("{ .reg .u64 t; cvta.to.shared.u64 t, %1; cvt.u32.u64 %0, t; }" : "=r"(a) : "l"(p));
    return a;
}

#define LDSM4(r, addr)                                                        \
    asm volatile("ldmatrix.sync.aligned.m8n8.x4.shared.b16 {%0,%1,%2,%3}, [%4];" \
                 : "=r"((r)[0]), "=r"((r)[1]), "=r"((r)[2]), "=r"((r)[3])     \
                 : "r"(addr))

#define MMA16816(d, a, b0, b1)                                                \
    asm volatile("mma.sync.aligned.m16n8k16.row.col.f32.bf16.bf16.f32 "       \
                 "{%0,%1,%2,%3},{%4,%5,%6,%7},{%8,%9},{%0,%1,%2,%3};"         \
                 : "+f"((d)[0]), "+f"((d)[1]), "+f"((d)[2]), "+f"((d)[3])     \
                 : "r"((a)[0]), "r"((a)[1]), "r"((a)[2]), "r"((a)[3]),        \
                   "r"(b0), "r"(b1))

#define CP_ASYNC16(saddr, gptr)                                               \
    asm volatile("cp.async.cg.shared.global [%0], [%1], 16;"                  \
                 :: "r"(saddr), "l"(gptr))
#define CP_COMMIT()  asm volatile("cp.async.commit_group;" ::: "memory")
#define CP_WAIT0()   asm volatile("cp.async.wait_group 0;" ::: "memory")

__device__ __forceinline__ uint32_t pack_bf16x2(__nv_bfloat16 a, __nv_bfloat16 b) {
    uint32_t r;
    asm("mov.b32 %0, {%1, %2};" : "=r"(r)
        : "h"(*(unsigned short*)&a), "h"(*(unsigned short*)&b));
    return r;
}

__device__ __forceinline__ void split_store8(char* hi_p, char* lo_p, float4 v) {
    __nv_bfloat16 h0 = __float2bfloat16(v.x), h1 = __float2bfloat16(v.y);
    __nv_bfloat16 h2 = __float2bfloat16(v.z), h3 = __float2bfloat16(v.w);
    __nv_bfloat16 l0 = __float2bfloat16(v.x - __bfloat162float(h0));
    __nv_bfloat16 l1 = __float2bfloat16(v.y - __bfloat162float(h1));
    __nv_bfloat16 l2 = __float2bfloat16(v.z - __bfloat162float(h2));
    __nv_bfloat16 l3 = __float2bfloat16(v.w - __bfloat162float(h3));
    *(uint2*)hi_p = make_uint2(pack_bf16x2(h0, h1), pack_bf16x2(h2, h3));
    *(uint2*)lo_p = make_uint2(pack_bf16x2(l0, l1), pack_bf16x2(l2, l3));
}

__device__ __forceinline__ float4 relu4(float4 v) {
    v.x = fmaxf(v.x, 0.f); v.y = fmaxf(v.y, 0.f);
    v.z = fmaxf(v.z, 0.f); v.w = fmaxf(v.w, 0.f);
    return v;
}

// ---------------- setup0: zero counters + build both weight images -----------
__global__ void setup0(const float* __restrict__ W1, const float* __restrict__ root1,
                       const float* __restrict__ W2, const float* __restrict__ root2)
{
    int idx = blockIdx.x * blockDim.x + threadIdx.x;
    if (idx == 0) g_total = 0;
    if (idx < N_NODES * N_REL) { g_cnt[idx] = 0; g_cursor[idx] = 0; }
    if (idx < 5 * 128 * 128) {
        int batch = idx / 16384, r = idx % 16384;
        int k = r / 128, n = r % 128;
        float v = (batch < 4) ? W1[(size_t)batch * 16384 + k * 128 + n] : root1[k * 128 + n];
        __nv_bfloat16 hi = __float2bfloat16(v);
        __nv_bfloat16 lo = __float2bfloat16(v - __bfloat162float(hi));
        size_t off = (size_t)batch * B1_IMG_BYTES + (size_t)n * ROW_BYTES + (size_t)k * 2;
        *(__nv_bfloat16*)((char*)g_B1hi + off) = hi;
        *(__nv_bfloat16*)((char*)g_B1lo + off) = lo;
    }
    if (idx < 5 * 128 * 96) {
        int batch = idx / 12288, r = idx % 12288;
        int k = r / 96, n = r % 96;
        float v = (batch < 4) ? W2[(size_t)batch * 12288 + k * 96 + n] : root2[k * 96 + n];
        __nv_bfloat16 hi = __float2bfloat16(v);
        __nv_bfloat16 lo = __float2bfloat16(v - __bfloat162float(hi));
        size_t off = (size_t)batch * B2_IMG_BYTES + (size_t)n * ROW_BYTES + (size_t)k * 2;
        *(__nv_bfloat16*)((char*)g_B2hi + off) = hi;
        *(__nv_bfloat16*)((char*)g_B2lo + off) = lo;
    }
}

__global__ void count_kernel(const int* __restrict__ ei, const int* __restrict__ et) {
    int e = blockIdx.x * blockDim.x + threadIdx.x;
    if (e < N_EDGES) atomicAdd(&g_cnt[ei[N_EDGES + e] * N_REL + et[e]], 1);
}

// per-dst base allocation: contiguity is all that matters, order is arbitrary
__global__ void alloc_base_kernel() {
    int d = blockIdx.x * blockDim.x + threadIdx.x;
    if (d < N_NODES) {
        int deg = g_cnt[d*4] + g_cnt[d*4+1] + g_cnt[d*4+2] + g_cnt[d*4+3];
        g_base[d] = atomicAdd(&g_total, deg);
    }
}

__global__ void reorder_kernel(const int* __restrict__ ei, const int* __restrict__ et) {
    int e = blockIdx.x * blockDim.x + threadIdx.x;
    if (e >= N_EDGES) return;
    int src = ei[e];
    int dst = ei[N_EDGES + e];
    int t   = et[e];
    int pos = atomicAdd(&g_cursor[dst * N_REL + t], 1);
    int sub = 0;
#pragma unroll
    for (int j = 0; j < N_REL - 1; j++) if (j < t) sub += g_cnt[dst * N_REL + j];
    g_csr[g_base[dst] + sub + pos] = (uint32_t)src;
}

// ---------------- fused aggregate+GEMM (64-row tiles, 2 CTAs/SM) -------------
// 256 threads, 8 warps (2 M x 4 N). Warp w stages rows w*8..+7 in TWO quad
// groups: 4 rows' edge walks interleaved -> MLP 4x, serial chain 2 L2/batch.
template <int DOUT, int SRC>   // SRC 0: feats = x (ext); 1: feats = relu(g_out1)
__global__ __launch_bounds__(256, 2)
void gemm_fused(const float* __restrict__ xext, const float* __restrict__ bias,
                float* __restrict__ out_ext)
{
    constexpr int B_IMG = (DOUT == 128) ? B1_IMG_BYTES : B2_IMG_BYTES;
    constexpr int B_U4  = B_IMG / 16;
    extern __shared__ char smem[];
    char* sAhi = smem;
    char* sAlo = smem + A_IMG_BYTES;

    int tid = threadIdx.x;
    int wid = tid >> 5, lane = tid & 31;
    int tile = blockIdx.x;

    const float* feats = (SRC == 0) ? xext : g_out1;
    float* Obuf = (DOUT == 128) ? g_out1 : out_ext;

    int warp_m = (wid & 1) * 32;
    int warp_n = (wid >> 1) * 32;
    bool active = (warp_n < DOUT);

    // ---- preload cnt/base for this warp's 8 rows (row = lane&7) ------------
    int my_row = wid * 8 + (lane & 7);
    int my_d   = tile * TILE_M + my_row;
    int4 cw = make_int4(0, 0, 0, 0);
    int  bs = 0;
    if (my_d < N_NODES) {
        cw = *(const int4*)&g_cnt[my_d * 4];
        bs = g_base[my_d];
    }
    int ps1 = cw.x, ps2 = cw.x + cw.y, ps3 = ps2 + cw.z;
    int deg_total = ps3 + cw.w;

    // ---- preload edge lists: lane-parallel, one LDG per row (MLP-8) --------
    uint32_t eidx[8];
#pragma unroll
    for (int i = 0; i < 8; i++) {
        int base = __shfl_sync(0xFFFFFFFFu, bs, i);
        int deg  = __shfl_sync(0xFFFFFFFFu, deg_total, i);
        eidx[i] = (lane < deg) ? g_csr[base + lane] : 0u;
    }

    uint32_t sb = smem_u32(smem);
    uint32_t aoff = (uint32_t)(warp_m + (lane & 15)) * ROW_BYTES + ((lane >> 4) & 1) * 16;
    uint32_t boff = (uint32_t)(warp_n + (lane & 7) + ((lane >> 4) & 1) * 8) * ROW_BYTES
                  + ((lane >> 3) & 1) * 16;
    uint32_t sBhi_base = sb + 2 * A_IMG_BYTES;
    uint32_t sBlo_base = sb + 2 * A_IMG_BYTES + B_IMG;

    float acc[2][4][4];
#pragma unroll
    for (int i = 0; i < 2; i++)
#pragma unroll
        for (int j = 0; j < 4; j++)
#pragma unroll
            for (int q = 0; q < 4; q++) acc[i][j][q] = 0.f;

#pragma unroll 1
    for (int batch = 0; batch < 5; batch++) {
        if (batch > 0) __syncthreads();   // prior MMA done reading smem

        // ---- B stage via cp.async: hides under the gather below ------------
        {
            const uint4* bhi = (DOUT == 128 ? g_B1hi : g_B2hi) + (size_t)batch * B_U4;
            const uint4* blo = (DOUT == 128 ? g_B1lo : g_B2lo) + (size_t)batch * B_U4;
            for (int i = tid; i < B_U4; i += 256) {
                CP_ASYNC16(sBhi_base + i * 16, bhi + i);
                CP_ASYNC16(sBlo_base + i * 16, blo + i);
            }
            CP_COMMIT();
        }

        if (batch < 4) {
            int c_sel   = (batch == 0) ? cw.x : (batch == 1) ? cw.y
                        : (batch == 2) ? cw.z : cw.w;
            int sub_sel = (batch == 0) ? 0 : (batch == 1) ? ps1
                        : (batch == 2) ? ps2 : ps3;
#pragma unroll
            for (int g = 0; g < 2; g++) {
                int c[4], sub[4];
                bool fast[4];
                float4 av[4];
#pragma unroll
                for (int r = 0; r < 4; r++) {
                    c[r]   = __shfl_sync(0xFFFFFFFFu, c_sel,   g * 4 + r);
                    sub[r] = __shfl_sync(0xFFFFFFFFu, sub_sel, g * 4 + r);
                    fast[r] = (sub[r] + c[r] <= 32);
                    av[r] = make_float4(0.f, 0.f, 0.f, 0.f);
                }
                int cmax = 0;
#pragma unroll
                for (int r = 0; r < 4; r++) {
                    int cf = fast[r] ? c[r] : 0;
                    cmax = cf > cmax ? cf : cmax;
                }
                // interleaved walk: up to 4 independent gathers per iteration
                for (int e = 0; e < cmax; e++) {
#pragma unroll
                    for (int r = 0; r < 4; r++) {
                        if (fast[r] && e < c[r]) {
                            int s = __shfl_sync(0xFFFFFFFFu, eidx[g * 4 + r], sub[r] + e);
                            float4 v = ((const float4*)(feats + (size_t)s * 128))[lane];
                            if (SRC == 1) v = relu4(v);
                            av[r].x += v.x; av[r].y += v.y;
                            av[r].z += v.z; av[r].w += v.w;
                        }
                    }
                }
                // rare slow rows (edge list spilled past 32)
#pragma unroll
                for (int r = 0; r < 4; r++) {
                    if (!fast[r]) {
                        int base = __shfl_sync(0xFFFFFFFFu, bs, g * 4 + r);
                        const uint32_t* ep = g_csr + base + sub[r];
                        for (int e = 0; e < c[r]; e++) {
                            int s = ep[e];
                            float4 v = ((const float4*)(feats + (size_t)s * 128))[lane];
                            if (SRC == 1) v = relu4(v);
                            av[r].x += v.x; av[r].y += v.y;
                            av[r].z += v.z; av[r].w += v.w;
                        }
                    }
                    float nm = 1.f / (float)(c[r] > 1 ? c[r] : 1);
                    av[r].x *= nm; av[r].y *= nm; av[r].z *= nm; av[r].w *= nm;
                    int dl = wid * 8 + g * 4 + r;
                    split_store8(sAhi + (size_t)dl * ROW_BYTES + lane * 8,
                                 sAlo + (size_t)dl * ROW_BYTES + lane * 8, av[r]);
                }
            }
        } else {
            // root batch: coalesced own-feature rows, 8 independent loads
#pragma unroll
            for (int i = 0; i < 8; i++) {
                int dl = wid * 8 + i;
                int d  = tile * TILE_M + dl;
                float4 a = make_float4(0.f, 0.f, 0.f, 0.f);
                if (d < N_NODES) {
                    a = ((const float4*)(feats + (size_t)d * 128))[lane];
                    if (SRC == 1) a = relu4(a);
                }
                split_store8(sAhi + (size_t)dl * ROW_BYTES + lane * 8,
                             sAlo + (size_t)dl * ROW_BYTES + lane * 8, a);
            }
        }

        CP_WAIT0();
        __syncthreads();

        // ---- MMA: accumulate this batch into persistent acc ----------------
        if (active) {
            uint32_t aA[2][2], bA[2][2];
#pragma unroll
            for (int s = 0; s < 2; s++) {
#pragma unroll
                for (int i = 0; i < 2; i++)
                    aA[s][i] = sb + s * A_IMG_BYTES + aoff + i * 16 * ROW_BYTES;
#pragma unroll
                for (int jj = 0; jj < 2; jj++)
                    bA[s][jj] = sb + 2 * A_IMG_BYTES + s * B_IMG + boff + jj * 16 * ROW_BYTES;
            }
#pragma unroll
            for (int kk = 0; kk < 8; kk++) {
                uint32_t ah[2][4], al[2][4], bh[2][4], bl[2][4];
#pragma unroll
                for (int i = 0; i < 2; i++) {
                    LDSM4(ah[i], aA[0][i]);
                    LDSM4(al[i], aA[1][i]);
                    aA[0][i] += 32; aA[1][i] += 32;
                }
#pragma unroll
                for (int jj = 0; jj < 2; jj++) {
                    LDSM4(bh[jj], bA[0][jj]);
                    LDSM4(bl[jj], bA[1][jj]);
                    bA[0][jj] += 32; bA[1][jj] += 32;
                }
#pragma unroll
                for (int i = 0; i < 2; i++) {
#pragma unroll
                    for (int j = 0; j < 4; j++) {
                        int jj = j >> 1, q = (j & 1) * 2;
                        MMA16816(acc[i][j], ah[i], bh[jj][q], bh[jj][q + 1]);
                        MMA16816(acc[i][j], ah[i], bl[jj][q], bl[jj][q + 1]);
                        MMA16816(acc[i][j], al[i], bh[jj][q], bh[jj][q + 1]);
                    }
                }
            }
        }
    }

    // ---- epilogue: complete layer output = agg + root + bias ---------------
    if (active) {
#pragma unroll
        for (int i = 0; i < 2; i++) {
            int row0 = tile * TILE_M + warp_m + i * 16 + (lane >> 2);
#pragma unroll
            for (int j = 0; j < 4; j++) {
                int col = warp_n + j * 8 + (lane & 3) * 2;
                if (col >= DOUT) continue;
                float b0 = bias[col], b1 = bias[col + 1];
                float2 v0 = make_float2(acc[i][j][0] + b0, acc[i][j][1] + b1);
                float2 v1 = make_float2(acc[i][j][2] + b0, acc[i][j][3] + b1);
                if (row0 < N_NODES)
                    *(float2*)(Obuf + (size_t)row0 * DOUT + col) = v0;
                if (row0 + 8 < N_NODES)
                    *(float2*)(Obuf + (size_t)(row0 + 8) * DOUT + col) = v1;
            }
        }
    }
}

// ---------------- launch -----------------------------------------------------
#define SMEM1 (2 * A_IMG_BYTES + 2 * B1_IMG_BYTES)   // 104448 -> 2 CTAs/SM
#define SMEM2 (2 * A_IMG_BYTES + 2 * B2_IMG_BYTES)   // 87040  -> 2 CTAs/SM

extern "C" void kernel_launch(void* const* d_in, const int* in_sizes, int n_in,
                              void* d_out, int out_size)
{
    const float* x     = (const float*)d_in[0];
    const int*   ei    = (const int*)d_in[1];
    const int*   et    = (const int*)d_in[2];
    const float* W1    = (const float*)d_in[3];
    const float* root1 = (const float*)d_in[4];
    const float* b1    = (const float*)d_in[5];
    const float* W2    = (const float*)d_in[6];
    const float* root2 = (const float*)d_in[7];
    const float* b2    = (const float*)d_in[8];
    float* out = (float*)d_out;

    cudaFuncSetAttribute(gemm_fused<128,0>, cudaFuncAttributeMaxDynamicSharedMemorySize, SMEM1);
    cudaFuncSetAttribute(gemm_fused<96,1>,  cudaFuncAttributeMaxDynamicSharedMemorySize, SMEM2);

    // 1: zero counters + weight images; 2: count; 3: base alloc; 4: reorder
    setup0<<<(N_NODES * N_REL + 255) / 256, 256>>>(W1, root1, W2, root2);
    count_kernel<<<(N_EDGES + 255) / 256, 256>>>(ei, et);
    alloc_base_kernel<<<(N_NODES + 255) / 256, 256>>>();
    reorder_kernel<<<(N_EDGES + 255) / 256, 256>>>(ei, et);

    // 5: layer 1 (out1 = RGCN(x), pre-relu); 6: layer 2 (out = RGCN(relu(out1)))
    gemm_fused<128,0><<<N_TILES64, 256, SMEM1>>>(x, b1, nullptr);
    gemm_fused<96,1><<<N_TILES64, 256, SMEM2>>>(nullptr, b2, out);
}

// round 14
// speedup vs baseline: 1.3463x; 1.3463x over previous
#include <cuda_runtime.h>
#include <cuda_bf16.h>
#include <cstdint>

#define N_NODES 100000
#define N_EDGES 600000
#define D_IN    128
#define D_OUT   96
#define N_REL   4

#define TILE_M    64
#define N_TILES64 1563               // ceil(100000/64)

#define ROW_BYTES 272                // 128 bf16 (256B) + 16B pad -> conflict-free ldmatrix
#define A_IMG_BYTES (TILE_M * ROW_BYTES)   // 17408
#define B1_ROWS 128
#define B2_ROWS 96
#define B1_IMG_BYTES (B1_ROWS * ROW_BYTES) // 34816
#define B2_IMG_BYTES (B2_ROWS * ROW_BYTES) // 26112

// ---------------- scratch (static device globals; no allocs allowed) --------
// NOTE: zero-initialized at module load; tail_zero re-zeroes after every run.
__device__ __align__(16) float g_out1[(size_t)N_NODES * D_IN];          // 51.2 MB
__device__ int      g_cnt[N_NODES * N_REL];
__device__ int      g_cursor[N_NODES * N_REL];
__device__ int      g_base[N_NODES];
__device__ int      g_total;
__device__ uint32_t g_csr[N_EDGES];

// weight images (bf16 hi/lo, padded rows). B2 rows 96 only.
__device__ uint4 g_B1hi[5 * (B1_IMG_BYTES / 16)];
__device__ uint4 g_B1lo[5 * (B1_IMG_BYTES / 16)];
__device__ uint4 g_B2hi[5 * (B2_IMG_BYTES / 16)];
__device__ uint4 g_B2lo[5 * (B2_IMG_BYTES / 16)];

// ---------------- helpers ----------------------------------------------------
__device__ __forceinline__ uint32_t smem_u32(const void* p) {
    uint32_t a;
    asm("{ .reg .u64 t; cvta.to.shared.u64 t, %1; cvt.u32.u64 %0, t; }" : "=r"(a) : "l"(p));
    return a;
}

#define LDSM4(r, addr)                                                        \
    asm volatile("ldmatrix.sync.aligned.m8n8.x4.shared.b16 {%0,%1,%2,%3}, [%4];" \
                 : "=r"((r)[0]), "=r"((r)[1]), "=r"((r)[2]), "=r"((r)[3])     \
                 : "r"(addr))

#define MMA16816(d, a, b0, b1)                                                \
    asm volatile("mma.sync.aligned.m16n8k16.row.col.f32.bf16.bf16.f32 "       \
                 "{%0,%1,%2,%3},{%4,%5,%6,%7},{%8,%9},{%0,%1,%2,%3};"         \
                 : "+f"((d)[0]), "+f"((d)[1]), "+f"((d)[2]), "+f"((d)[3])     \
                 : "r"((a)[0]), "r"((a)[1]), "r"((a)[2]), "r"((a)[3]),        \
                   "r"(b0), "r"(b1))

#define CP_ASYNC16(saddr, gptr)                                               \
    asm volatile("cp.async.cg.shared.global [%0], [%1], 16;"                  \
                 :: "r"(saddr), "l"(gptr))
#define CP_COMMIT()  asm volatile("cp.async.commit_group;" ::: "memory")
#define CP_WAIT0()   asm volatile("cp.async.wait_group 0;" ::: "memory")

__device__ __forceinline__ uint32_t pack_bf16x2(__nv_bfloat16 a, __nv_bfloat16 b) {
    uint32_t r;
    asm("mov.b32 %0, {%1, %2};" : "=r"(r)
        : "h"(*(unsigned short*)&a), "h"(*(unsigned short*)&b));
    return r;
}

__device__ __forceinline__ void split_store8(char* hi_p, char* lo_p, float4 v) {
    __nv_bfloat16 h0 = __float2bfloat16(v.x), h1 = __float2bfloat16(v.y);
    __nv_bfloat16 h2 = __float2bfloat16(v.z), h3 = __float2bfloat16(v.w);
    __nv_bfloat16 l0 = __float2bfloat16(v.x - __bfloat162float(h0));
    __nv_bfloat16 l1 = __float2bfloat16(v.y - __bfloat162float(h1));
    __nv_bfloat16 l2 = __float2bfloat16(v.z - __bfloat162float(h2));
    __nv_bfloat16 l3 = __float2bfloat16(v.w - __bfloat162float(h3));
    *(uint2*)hi_p = make_uint2(pack_bf16x2(h0, h1), pack_bf16x2(h2, h3));
    *(uint2*)lo_p = make_uint2(pack_bf16x2(l0, l1), pack_bf16x2(l2, l3));
}

__device__ __forceinline__ float4 relu4(float4 v) {
    v.x = fmaxf(v.x, 0.f); v.y = fmaxf(v.y, 0.f);
    v.z = fmaxf(v.z, 0.f); v.w = fmaxf(v.w, 0.f);
    return v;
}

// ---------------- launch 1: edge count + weight image build ------------------
// Counters are guaranteed zero on entry (module-load init / tail_zero).
__global__ void count_prep(const int* __restrict__ ei, const int* __restrict__ et,
                           const float* __restrict__ W1, const float* __restrict__ root1,
                           const float* __restrict__ W2, const float* __restrict__ root2)
{
    int idx = blockIdx.x * blockDim.x + threadIdx.x;
    if (idx < N_EDGES) atomicAdd(&g_cnt[ei[N_EDGES + idx] * N_REL + et[idx]], 1);
    if (idx < 5 * 128 * 128) {
        int batch = idx / 16384, r = idx % 16384;
        int k = r / 128, n = r % 128;
        float v = (batch < 4) ? W1[(size_t)batch * 16384 + k * 128 + n] : root1[k * 128 + n];
        __nv_bfloat16 hi = __float2bfloat16(v);
        __nv_bfloat16 lo = __float2bfloat16(v - __bfloat162float(hi));
        size_t off = (size_t)batch * B1_IMG_BYTES + (size_t)n * ROW_BYTES + (size_t)k * 2;
        *(__nv_bfloat16*)((char*)g_B1hi + off) = hi;
        *(__nv_bfloat16*)((char*)g_B1lo + off) = lo;
    }
    if (idx < 5 * 128 * 96) {
        int batch = idx / 12288, r = idx % 12288;
        int k = r / 96, n = r % 96;
        float v = (batch < 4) ? W2[(size_t)batch * 12288 + k * 96 + n] : root2[k * 96 + n];
        __nv_bfloat16 hi = __float2bfloat16(v);
        __nv_bfloat16 lo = __float2bfloat16(v - __bfloat162float(hi));
        size_t off = (size_t)batch * B2_IMG_BYTES + (size_t)n * ROW_BYTES + (size_t)k * 2;
        *(__nv_bfloat16*)((char*)g_B2hi + off) = hi;
        *(__nv_bfloat16*)((char*)g_B2lo + off) = lo;
    }
}

// ---------------- launch 2: per-dst base allocation (order-free) -------------
__global__ void alloc_base_kernel() {
    int d = blockIdx.x * blockDim.x + threadIdx.x;
    if (d < N_NODES) {
        int deg = g_cnt[d*4] + g_cnt[d*4+1] + g_cnt[d*4+2] + g_cnt[d*4+3];
        g_base[d] = atomicAdd(&g_total, deg);
    }
}

// ---------------- launch 3: CSR reorder --------------------------------------
__global__ void reorder_kernel(const int* __restrict__ ei, const int* __restrict__ et) {
    int e = blockIdx.x * blockDim.x + threadIdx.x;
    if (e >= N_EDGES) return;
    int src = ei[e];
    int dst = ei[N_EDGES + e];
    int t   = et[e];
    int pos = atomicAdd(&g_cursor[dst * N_REL + t], 1);
    int sub = 0;
#pragma unroll
    for (int j = 0; j < N_REL - 1; j++) if (j < t) sub += g_cnt[dst * N_REL + j];
    g_csr[g_base[dst] + sub + pos] = (uint32_t)src;
}

// ---------------- launch 6: tail zero (restores invariant for next run) ------
__global__ void tail_zero() {
    int i = blockIdx.x * blockDim.x + threadIdx.x;
    if (i == 0) g_total = 0;
    if (i < N_NODES * N_REL) { g_cnt[i] = 0; g_cursor[i] = 0; }
}

// ---------------- launches 4+5: fused aggregate+GEMM (R11 staging) -----------
// 64-row tiles, 2 CTAs/SM, 256 threads, 8 warps (2M x 4N), warp tile 32x32.
// Edge lists preloaded lane-parallel into registers (1 LDG/row); B via cp.async.
template <int DOUT, int SRC>   // SRC 0: feats = x (ext); 1: feats = relu(g_out1)
__global__ __launch_bounds__(256, 2)
void gemm_fused(const float* __restrict__ xext, const float* __restrict__ bias,
                float* __restrict__ out_ext)
{
    constexpr int B_IMG = (DOUT == 128) ? B1_IMG_BYTES : B2_IMG_BYTES;
    constexpr int B_U4  = B_IMG / 16;
    extern __shared__ char smem[];
    char* sAhi = smem;
    char* sAlo = smem + A_IMG_BYTES;

    int tid = threadIdx.x;
    int wid = tid >> 5, lane = tid & 31;
    int tile = blockIdx.x;

    const float* feats = (SRC == 0) ? xext : g_out1;
    float* Obuf = (DOUT == 128) ? g_out1 : out_ext;

    int warp_m = (wid & 1) * 32;
    int warp_n = (wid >> 1) * 32;
    bool active = (warp_n < DOUT);

    // ---- preload cnt/base for this warp's 8 rows (row = lane&7) ------------
    int my_row = wid * 8 + (lane & 7);
    int my_d   = tile * TILE_M + my_row;
    int4 cw = make_int4(0, 0, 0, 0);
    int  bs = 0;
    if (my_d < N_NODES) {
        cw = *(const int4*)&g_cnt[my_d * 4];
        bs = g_base[my_d];
    }
    int ps1 = cw.x, ps2 = cw.x + cw.y, ps3 = ps2 + cw.z;
    int deg_total = ps3 + cw.w;

    // ---- preload edge lists: lane-parallel, one LDG per row (MLP-8) --------
    uint32_t eidx[8];
#pragma unroll
    for (int i = 0; i < 8; i++) {
        int base = __shfl_sync(0xFFFFFFFFu, bs, i);
        int deg  = __shfl_sync(0xFFFFFFFFu, deg_total, i);
        eidx[i] = (lane < deg) ? g_csr[base + lane] : 0u;
    }

    uint32_t sb = smem_u32(smem);
    uint32_t aoff = (uint32_t)(warp_m + (lane & 15)) * ROW_BYTES + ((lane >> 4) & 1) * 16;
    uint32_t boff = (uint32_t)(warp_n + (lane & 7) + ((lane >> 4) & 1) * 8) * ROW_BYTES
                  + ((lane >> 3) & 1) * 16;
    uint32_t sBhi_base = sb + 2 * A_IMG_BYTES;
    uint32_t sBlo_base = sb + 2 * A_IMG_BYTES + B_IMG;

    float acc[2][4][4];
#pragma unroll
    for (int i = 0; i < 2; i++)
#pragma unroll
        for (int j = 0; j < 4; j++)
#pragma unroll
            for (int q = 0; q < 4; q++) acc[i][j][q] = 0.f;

#pragma unroll 1
    for (int batch = 0; batch < 5; batch++) {
        if (batch > 0) __syncthreads();   // prior MMA done reading smem

        // ---- B stage via cp.async: hides under the gather below ------------
        {
            const uint4* bhi = (DOUT == 128 ? g_B1hi : g_B2hi) + (size_t)batch * B_U4;
            const uint4* blo = (DOUT == 128 ? g_B1lo : g_B2lo) + (size_t)batch * B_U4;
            for (int i = tid; i < B_U4; i += 256) {
                CP_ASYNC16(sBhi_base + i * 16, bhi + i);
                CP_ASYNC16(sBlo_base + i * 16, blo + i);
            }
            CP_COMMIT();
        }

        int c_sel   = (batch == 0) ? cw.x : (batch == 1) ? cw.y
                    : (batch == 2) ? cw.z : cw.w;
        int sub_sel = (batch == 0) ? 0 : (batch == 1) ? ps1
                    : (batch == 2) ? ps2 : ps3;

        // ---- stage A: warp w owns rows w*8..w*8+7 (R11 serial-row form) ----
#pragma unroll 1
        for (int i = 0; i < 8; i++) {
            int dl = wid * 8 + i;
            int d  = tile * TILE_M + dl;
            float4 a = make_float4(0.f, 0.f, 0.f, 0.f);
            if (d < N_NODES) {
                if (batch < 4) {
                    int c   = __shfl_sync(0xFFFFFFFFu, c_sel,   i);
                    int sub = __shfl_sync(0xFFFFFFFFu, sub_sel, i);
                    float4 a1 = make_float4(0.f,0.f,0.f,0.f);
                    if (sub + c <= 32) {
                        // fast path: indices register-resident via shfl
                        int e = 0;
                        for (; e + 1 < c; e += 2) {
                            int s0 = __shfl_sync(0xFFFFFFFFu, eidx[i], sub + e);
                            int s1 = __shfl_sync(0xFFFFFFFFu, eidx[i], sub + e + 1);
                            float4 v0 = ((const float4*)(feats + (size_t)s0 * 128))[lane];
                            float4 v1 = ((const float4*)(feats + (size_t)s1 * 128))[lane];
                            if (SRC == 1) { v0 = relu4(v0); v1 = relu4(v1); }
                            a.x += v0.x;  a.y += v0.y;  a.z += v0.z;  a.w += v0.w;
                            a1.x += v1.x; a1.y += v1.y; a1.z += v1.z; a1.w += v1.w;
                        }
                        if (e < c) {
                            int s0 = __shfl_sync(0xFFFFFFFFu, eidx[i], sub + e);
                            float4 v0 = ((const float4*)(feats + (size_t)s0 * 128))[lane];
                            if (SRC == 1) v0 = relu4(v0);
                            a.x += v0.x; a.y += v0.y; a.z += v0.z; a.w += v0.w;
                        }
                    } else {
                        // rare fallback: memory walk
                        int base = __shfl_sync(0xFFFFFFFFu, bs, i);
                        const uint32_t* ep = g_csr + base + sub;
                        for (int e = 0; e < c; e++) {
                            int s0 = ep[e];
                            float4 v0 = ((const float4*)(feats + (size_t)s0 * 128))[lane];
                            if (SRC == 1) v0 = relu4(v0);
                            a.x += v0.x; a.y += v0.y; a.z += v0.z; a.w += v0.w;
                        }
                    }
                    float nm = 1.f / (float)(c > 1 ? c : 1);
                    a.x = (a.x + a1.x) * nm; a.y = (a.y + a1.y) * nm;
                    a.z = (a.z + a1.z) * nm; a.w = (a.w + a1.w) * nm;
                } else {
                    a = ((const float4*)(feats + (size_t)d * 128))[lane];
                    if (SRC == 1) a = relu4(a);
                }
            }
            split_store8(sAhi + (size_t)dl * ROW_BYTES + lane * 8,
                         sAlo + (size_t)dl * ROW_BYTES + lane * 8, a);
        }

        CP_WAIT0();
        __syncthreads();

        // ---- MMA: accumulate this batch into persistent acc ----------------
        if (active) {
            uint32_t aA[2][2], bA[2][2];
#pragma unroll
            for (int s = 0; s < 2; s++) {
#pragma unroll
                for (int i = 0; i < 2; i++)
                    aA[s][i] = sb + s * A_IMG_BYTES + aoff + i * 16 * ROW_BYTES;
#pragma unroll
                for (int jj = 0; jj < 2; jj++)
                    bA[s][jj] = sb + 2 * A_IMG_BYTES + s * B_IMG + boff + jj * 16 * ROW_BYTES;
            }
#pragma unroll
            for (int kk = 0; kk < 8; kk++) {
                uint32_t ah[2][4], al[2][4], bh[2][4], bl[2][4];
#pragma unroll
                for (int i = 0; i < 2; i++) {
                    LDSM4(ah[i], aA[0][i]);
                    LDSM4(al[i], aA[1][i]);
                    aA[0][i] += 32; aA[1][i] += 32;
                }
#pragma unroll
                for (int jj = 0; jj < 2; jj++) {
                    LDSM4(bh[jj], bA[0][jj]);
                    LDSM4(bl[jj], bA[1][jj]);
                    bA[0][jj] += 32; bA[1][jj] += 32;
                }
#pragma unroll
                for (int i = 0; i < 2; i++) {
#pragma unroll
                    for (int j = 0; j < 4; j++) {
                        int jj = j >> 1, q = (j & 1) * 2;
                        MMA16816(acc[i][j], ah[i], bh[jj][q], bh[jj][q + 1]);
                        MMA16816(acc[i][j], ah[i], bl[jj][q], bl[jj][q + 1]);
                        MMA16816(acc[i][j], al[i], bh[jj][q], bh[jj][q + 1]);
                    }
                }
            }
        }
    }

    // ---- epilogue: complete layer output = agg + root + bias ---------------
    if (active) {
#pragma unroll
        for (int i = 0; i < 2; i++) {
            int row0 = tile * TILE_M + warp_m + i * 16 + (lane >> 2);
#pragma unroll
            for (int j = 0; j < 4; j++) {
                int col = warp_n + j * 8 + (lane & 3) * 2;
                if (col >= DOUT) continue;
                float b0 = bias[col], b1 = bias[col + 1];
                float2 v0 = make_float2(acc[i][j][0] + b0, acc[i][j][1] + b1);
                float2 v1 = make_float2(acc[i][j][2] + b0, acc[i][j][3] + b1);
                if (row0 < N_NODES)
                    *(float2*)(Obuf + (size_t)row0 * DOUT + col) = v0;
                if (row0 + 8 < N_NODES)
                    *(float2*)(Obuf + (size_t)(row0 + 8) * DOUT + col) = v1;
            }
        }
    }
}

// ---------------- launch -----------------------------------------------------
#define SMEM1 (2 * A_IMG_BYTES + 2 * B1_IMG_BYTES)   // 104448 -> 2 CTAs/SM
#define SMEM2 (2 * A_IMG_BYTES + 2 * B2_IMG_BYTES)   // 87040  -> 2 CTAs/SM

extern "C" void kernel_launch(void* const* d_in, const int* in_sizes, int n_in,
                              void* d_out, int out_size)
{
    const float* x     = (const float*)d_in[0];
    const int*   ei    = (const int*)d_in[1];
    const int*   et    = (const int*)d_in[2];
    const float* W1    = (const float*)d_in[3];
    const float* root1 = (const float*)d_in[4];
    const float* b1    = (const float*)d_in[5];
    const float* W2    = (const float*)d_in[6];
    const float* root2 = (const float*)d_in[7];
    const float* b2    = (const float*)d_in[8];
    float* out = (float*)d_out;

    cudaFuncSetAttribute(gemm_fused<128,0>, cudaFuncAttributeMaxDynamicSharedMemorySize, SMEM1);
    cudaFuncSetAttribute(gemm_fused<96,1>,  cudaFuncAttributeMaxDynamicSharedMemorySize, SMEM2);

    // counters are zero on entry (module-load init first call; tail_zero after).
    count_prep<<<(N_EDGES + 255) / 256, 256>>>(ei, et, W1, root1, W2, root2);  // #1
    alloc_base_kernel<<<(N_NODES + 255) / 256, 256>>>();                       // #2
    reorder_kernel<<<(N_EDGES + 255) / 256, 256>>>(ei, et);                    // #3
    gemm_fused<128,0><<<N_TILES64, 256, SMEM1>>>(x, b1, nullptr);              // #4 (profiled)
    gemm_fused<96,1><<<N_TILES64, 256, SMEM2>>>(nullptr, b2, out);             // #5
    tail_zero<<<(N_NODES * N_REL + 255) / 256, 256>>>();                       // #6
}

// round 16
// speedup vs baseline: 1.7212x; 1.2785x over previous
#include <cuda_runtime.h>
#include <cuda_bf16.h>
#include <cstdint>

#define N_NODES 100000
#define N_EDGES 600000
#define D_IN    128
#define D_OUT   96
#define N_REL   4

#define TILE_M    64
#define N_TILES64 1563               // ceil(100000/64)

#define ROW_BYTES 272                // 128 bf16 (256B) + 16B pad -> conflict-free ldmatrix
#define A_IMG_BYTES (TILE_M * ROW_BYTES)   // 17408
#define B1_ROWS 128
#define B2_ROWS 96
#define B1_IMG_BYTES (B1_ROWS * ROW_BYTES) // 34816
#define B2_IMG_BYTES (B2_ROWS * ROW_BYTES) // 26112

// ---------------- scratch (static device globals; no allocs allowed) --------
// NOTE: zero-initialized at module load; tail_zero re-zeroes after every run.
__device__ __align__(16) float g_out1[(size_t)N_NODES * D_IN];          // 51.2 MB
__device__ int      g_cnt[N_NODES * N_REL];
__device__ int      g_cursor[N_NODES * N_REL];
__device__ int      g_base[N_NODES];
__device__ int      g_total;
__device__ uint32_t g_csr[N_EDGES];

// weight images (bf16 hi/lo, padded rows). B2 rows 96 only.
__device__ uint4 g_B1hi[5 * (B1_IMG_BYTES / 16)];
__device__ uint4 g_B1lo[5 * (B1_IMG_BYTES / 16)];
__device__ uint4 g_B2hi[5 * (B2_IMG_BYTES / 16)];
__device__ uint4 g_B2lo[5 * (B2_IMG_BYTES / 16)];

// ---------------- helpers ----------------------------------------------------
__device__ __forceinline__ uint32_t smem_u32(const void* p) {
    uint32_t a;
    asm("{ .reg .u64 t; cvta.to.shared.u64 t, %1; cvt.u32.u64 %0, t; }" : "=r"(a) : "l"(p));
    return a;
}

#define LDSM4(r, addr)                                                        \
    asm volatile("ldmatrix.sync.aligned.m8n8.x4.shared.b16 {%0,%1,%2,%3}, [%4];" \
                 : "=r"((r)[0]), "=r"((r)[1]), "=r"((r)[2]), "=r"((r)[3])     \
                 : "r"(addr))

#define MMA16816(d, a, b0, b1)                                                \
    asm volatile("mma.sync.aligned.m16n8k16.row.col.f32.bf16.bf16.f32 "       \
                 "{%0,%1,%2,%3},{%4,%5,%6,%7},{%8,%9},{%0,%1,%2,%3};"         \
                 : "+f"((d)[0]), "+f"((d)[1]), "+f"((d)[2]), "+f"((d)[3])     \
                 : "r"((a)[0]), "r"((a)[1]), "r"((a)[2]), "r"((a)[3]),        \
                   "r"(b0), "r"(b1))

#define CP_ASYNC16(saddr, gptr)                                               \
    asm volatile("cp.async.cg.shared.global [%0], [%1], 16;"                  \
                 :: "r"(saddr), "l"(gptr))
#define CP_COMMIT()  asm volatile("cp.async.commit_group;" ::: "memory")
#define CP_WAIT0()   asm volatile("cp.async.wait_group 0;" ::: "memory")

__device__ __forceinline__ uint32_t pack_bf16x2(__nv_bfloat16 a, __nv_bfloat16 b) {
    uint32_t r;
    asm("mov.b32 %0, {%1, %2};" : "=r"(r)
        : "h"(*(unsigned short*)&a), "h"(*(unsigned short*)&b));
    return r;
}

__device__ __forceinline__ void split_store8(char* hi_p, char* lo_p, float4 v) {
    __nv_bfloat16 h0 = __float2bfloat16(v.x), h1 = __float2bfloat16(v.y);
    __nv_bfloat16 h2 = __float2bfloat16(v.z), h3 = __float2bfloat16(v.w);
    __nv_bfloat16 l0 = __float2bfloat16(v.x - __bfloat162float(h0));
    __nv_bfloat16 l1 = __float2bfloat16(v.y - __bfloat162float(h1));
    __nv_bfloat16 l2 = __float2bfloat16(v.z - __bfloat162float(h2));
    __nv_bfloat16 l3 = __float2bfloat16(v.w - __bfloat162float(h3));
    *(uint2*)hi_p = make_uint2(pack_bf16x2(h0, h1), pack_bf16x2(h2, h3));
    *(uint2*)lo_p = make_uint2(pack_bf16x2(l0, l1), pack_bf16x2(l2, l3));
}

__device__ __forceinline__ float4 relu4(float4 v) {
    v.x = fmaxf(v.x, 0.f); v.y = fmaxf(v.y, 0.f);
    v.z = fmaxf(v.z, 0.f); v.w = fmaxf(v.w, 0.f);
    return v;
}

// ---------------- launch 1: edge count + weight image build ------------------
__global__ void count_prep(const int* __restrict__ ei, const int* __restrict__ et,
                           const float* __restrict__ W1, const float* __restrict__ root1,
                           const float* __restrict__ W2, const float* __restrict__ root2)
{
    int idx = blockIdx.x * blockDim.x + threadIdx.x;
    if (idx < N_EDGES) atomicAdd(&g_cnt[ei[N_EDGES + idx] * N_REL + et[idx]], 1);
    if (idx < 5 * 128 * 128) {
        int batch = idx / 16384, r = idx % 16384;
        int k = r / 128, n = r % 128;
        float v = (batch < 4) ? W1[(size_t)batch * 16384 + k * 128 + n] : root1[k * 128 + n];
        __nv_bfloat16 hi = __float2bfloat16(v);
        __nv_bfloat16 lo = __float2bfloat16(v - __bfloat162float(hi));
        size_t off = (size_t)batch * B1_IMG_BYTES + (size_t)n * ROW_BYTES + (size_t)k * 2;
        *(__nv_bfloat16*)((char*)g_B1hi + off) = hi;
        *(__nv_bfloat16*)((char*)g_B1lo + off) = lo;
    }
    if (idx < 5 * 128 * 96) {
        int batch = idx / 12288, r = idx % 12288;
        int k = r / 96, n = r % 96;
        float v = (batch < 4) ? W2[(size_t)batch * 12288 + k * 96 + n] : root2[k * 96 + n];
        __nv_bfloat16 hi = __float2bfloat16(v);
        __nv_bfloat16 lo = __float2bfloat16(v - __bfloat162float(hi));
        size_t off = (size_t)batch * B2_IMG_BYTES + (size_t)n * ROW_BYTES + (size_t)k * 2;
        *(__nv_bfloat16*)((char*)g_B2hi + off) = hi;
        *(__nv_bfloat16*)((char*)g_B2lo + off) = lo;
    }
}

// ---------------- launch 2: per-dst base allocation (order-free) -------------
__global__ void alloc_base_kernel() {
    int d = blockIdx.x * blockDim.x + threadIdx.x;
    if (d < N_NODES) {
        int deg = g_cnt[d*4] + g_cnt[d*4+1] + g_cnt[d*4+2] + g_cnt[d*4+3];
        g_base[d] = atomicAdd(&g_total, deg);
    }
}

// ---------------- launch 3: CSR reorder --------------------------------------
__global__ void reorder_kernel(const int* __restrict__ ei, const int* __restrict__ et) {
    int e = blockIdx.x * blockDim.x + threadIdx.x;
    if (e >= N_EDGES) return;
    int src = ei[e];
    int dst = ei[N_EDGES + e];
    int t   = et[e];
    int pos = atomicAdd(&g_cursor[dst * N_REL + t], 1);
    int sub = 0;
#pragma unroll
    for (int j = 0; j < N_REL - 1; j++) if (j < t) sub += g_cnt[dst * N_REL + j];
    g_csr[g_base[dst] + sub + pos] = (uint32_t)src;
}

// ---------------- launch 6: tail zero (restores invariant for next run) ------
__global__ void tail_zero() {
    int i = blockIdx.x * blockDim.x + threadIdx.x;
    if (i == 0) g_total = 0;
    if (i < N_NODES * N_REL) { g_cnt[i] = 0; g_cursor[i] = 0; }
}

// ---------------- launches 4+5: fused aggregate+GEMM -------------------------
// 64-row tiles, 512 threads, 16 warps (4M x 4N), warp tile 16x32, 2 CTAs/SM
// -> 32 warps/SM. Warp w stages rows w*4..+3. Edge lists register-resident.
template <int DOUT, int SRC>   // SRC 0: feats = x (ext); 1: feats = relu(g_out1)
__global__ __launch_bounds__(512, 2)
void gemm_fused(const float* __restrict__ xext, const float* __restrict__ bias,
                float* __restrict__ out_ext)
{
    constexpr int B_IMG = (DOUT == 128) ? B1_IMG_BYTES : B2_IMG_BYTES;
    constexpr int B_U4  = B_IMG / 16;
    extern __shared__ char smem[];
    char* sAhi = smem;
    char* sAlo = smem + A_IMG_BYTES;

    int tid = threadIdx.x;
    int wid = tid >> 5, lane = tid & 31;
    int tile = blockIdx.x;

    const float* feats = (SRC == 0) ? xext : g_out1;
    float* Obuf = (DOUT == 128) ? g_out1 : out_ext;

    int warp_m = (wid & 3) * 16;
    int warp_n = (wid >> 2) * 32;
    bool active = (warp_n < DOUT);

    // ---- preload cnt/base for this warp's 4 rows (row = lane&3) ------------
    int my_row = wid * 4 + (lane & 3);
    int my_d   = tile * TILE_M + my_row;
    int4 cw = make_int4(0, 0, 0, 0);
    int  bs = 0;
    if (my_d < N_NODES) {
        cw = *(const int4*)&g_cnt[my_d * 4];
        bs = g_base[my_d];
    }
    int ps1 = cw.x, ps2 = cw.x + cw.y, ps3 = ps2 + cw.z;
    int deg_total = ps3 + cw.w;

    // ---- preload edge lists: lane-parallel, one LDG per row (MLP-4) --------
    uint32_t eidx[4];
#pragma unroll
    for (int i = 0; i < 4; i++) {
        int base = __shfl_sync(0xFFFFFFFFu, bs, i);
        int deg  = __shfl_sync(0xFFFFFFFFu, deg_total, i);
        eidx[i] = (lane < deg) ? g_csr[base + lane] : 0u;
    }

    uint32_t sb = smem_u32(smem);
    uint32_t aoff = (uint32_t)(warp_m + (lane & 15)) * ROW_BYTES + ((lane >> 4) & 1) * 16;
    uint32_t boff = (uint32_t)(warp_n + (lane & 7) + ((lane >> 4) & 1) * 8) * ROW_BYTES
                  + ((lane >> 3) & 1) * 16;
    uint32_t sBhi_base = sb + 2 * A_IMG_BYTES;
    uint32_t sBlo_base = sb + 2 * A_IMG_BYTES + B_IMG;

    float acc[4][4];
#pragma unroll
    for (int j = 0; j < 4; j++)
#pragma unroll
        for (int q = 0; q < 4; q++) acc[j][q] = 0.f;

#pragma unroll 1
    for (int batch = 0; batch < 5; batch++) {
        if (batch > 0) __syncthreads();   // prior MMA done reading smem

        // ---- B stage via cp.async: hides under the gather below ------------
        {
            const uint4* bhi = (DOUT == 128 ? g_B1hi : g_B2hi) + (size_t)batch * B_U4;
            const uint4* blo = (DOUT == 128 ? g_B1lo : g_B2lo) + (size_t)batch * B_U4;
            for (int i = tid; i < B_U4; i += 512) {
                CP_ASYNC16(sBhi_base + i * 16, bhi + i);
                CP_ASYNC16(sBlo_base + i * 16, blo + i);
            }
            CP_COMMIT();
        }

        int c_sel   = (batch == 0) ? cw.x : (batch == 1) ? cw.y
                    : (batch == 2) ? cw.z : cw.w;
        int sub_sel = (batch == 0) ? 0 : (batch == 1) ? ps1
                    : (batch == 2) ? ps2 : ps3;

        // ---- stage A: warp w owns rows w*4..w*4+3 --------------------------
#pragma unroll 1
        for (int i = 0; i < 4; i++) {
            int dl = wid * 4 + i;
            int d  = tile * TILE_M + dl;
            float4 a = make_float4(0.f, 0.f, 0.f, 0.f);
            if (d < N_NODES) {
                if (batch < 4) {
                    int c   = __shfl_sync(0xFFFFFFFFu, c_sel,   i);
                    int sub = __shfl_sync(0xFFFFFFFFu, sub_sel, i);
                    float4 a1 = make_float4(0.f,0.f,0.f,0.f);
                    if (sub + c <= 32) {
                        // fast path: indices register-resident via shfl
                        int e = 0;
                        for (; e + 1 < c; e += 2) {
                            int s0 = __shfl_sync(0xFFFFFFFFu, eidx[i], sub + e);
                            int s1 = __shfl_sync(0xFFFFFFFFu, eidx[i], sub + e + 1);
                            float4 v0 = ((const float4*)(feats + (size_t)s0 * 128))[lane];
                            float4 v1 = ((const float4*)(feats + (size_t)s1 * 128))[lane];
                            if (SRC == 1) { v0 = relu4(v0); v1 = relu4(v1); }
                            a.x += v0.x;  a.y += v0.y;  a.z += v0.z;  a.w += v0.w;
                            a1.x += v1.x; a1.y += v1.y; a1.z += v1.z; a1.w += v1.w;
                        }
                        if (e < c) {
                            int s0 = __shfl_sync(0xFFFFFFFFu, eidx[i], sub + e);
                            float4 v0 = ((const float4*)(feats + (size_t)s0 * 128))[lane];
                            if (SRC == 1) v0 = relu4(v0);
                            a.x += v0.x; a.y += v0.y; a.z += v0.z; a.w += v0.w;
                        }
                    } else {
                        // rare fallback: memory walk
                        int base = __shfl_sync(0xFFFFFFFFu, bs, i);
                        const uint32_t* ep = g_csr + base + sub;
                        for (int e = 0; e < c; e++) {
                            int s0 = ep[e];
                            float4 v0 = ((const float4*)(feats + (size_t)s0 * 128))[lane];
                            if (SRC == 1) v0 = relu4(v0);
                            a.x += v0.x; a.y += v0.y; a.z += v0.z; a.w += v0.w;
                        }
                    }
                    float nm = 1.f / (float)(c > 1 ? c : 1);
                    a.x = (a.x + a1.x) * nm; a.y = (a.y + a1.y) * nm;
                    a.z = (a.z + a1.z) * nm; a.w = (a.w + a1.w) * nm;
                } else {
                    a = ((const float4*)(feats + (size_t)d * 128))[lane];
                    if (SRC == 1) a = relu4(a);
                }
            }
            split_store8(sAhi + (size_t)dl * ROW_BYTES + lane * 8,
                         sAlo + (size_t)dl * ROW_BYTES + lane * 8, a);
        }

        CP_WAIT0();
        __syncthreads();

        // ---- MMA: accumulate this batch into persistent acc ----------------
        if (active) {
            uint32_t aA[2], bA[2][2];
#pragma unroll
            for (int s = 0; s < 2; s++) {
                aA[s] = sb + s * A_IMG_BYTES + aoff;
#pragma unroll
                for (int jj = 0; jj < 2; jj++)
                    bA[s][jj] = sb + 2 * A_IMG_BYTES + s * B_IMG + boff + jj * 16 * ROW_BYTES;
            }
#pragma unroll
            for (int kk = 0; kk < 8; kk++) {
                uint32_t ah[4], al[4], bh[2][4], bl[2][4];
                LDSM4(ah, aA[0]);
                LDSM4(al, aA[1]);
                aA[0] += 32; aA[1] += 32;
#pragma unroll
                for (int jj = 0; jj < 2; jj++) {
                    LDSM4(bh[jj], bA[0][jj]);
                    LDSM4(bl[jj], bA[1][jj]);
                    bA[0][jj] += 32; bA[1][jj] += 32;
                }
#pragma unroll
                for (int j = 0; j < 4; j++) {
                    int jj = j >> 1, q = (j & 1) * 2;
                    MMA16816(acc[j], ah, bh[jj][q], bh[jj][q + 1]);
                    MMA16816(acc[j], ah, bl[jj][q], bl[jj][q + 1]);
                    MMA16816(acc[j], al, bh[jj][q], bh[jj][q + 1]);
                }
            }
        }
    }

    // ---- epilogue: complete layer output = agg + root + bias ---------------
    if (active) {
        int row0 = tile * TILE_M + warp_m + (lane >> 2);
#pragma unroll
        for (int j = 0; j < 4; j++) {
            int col = warp_n + j * 8 + (lane & 3) * 2;
            if (col >= DOUT) continue;
            float b0 = bias[col], b1 = bias[col + 1];
            float2 v0 = make_float2(acc[j][0] + b0, acc[j][1] + b1);
            float2 v1 = make_float2(acc[j][2] + b0, acc[j][3] + b1);
            if (row0 < N_NODES)
                *(float2*)(Obuf + (size_t)row0 * DOUT + col) = v0;
            if (row0 + 8 < N_NODES)
                *(float2*)(Obuf + (size_t)(row0 + 8) * DOUT + col) = v1;
        }
    }
}

// ---------------- launch -----------------------------------------------------
#define SMEM1 (2 * A_IMG_BYTES + 2 * B1_IMG_BYTES)   // 104448 -> 2 CTAs/SM
#define SMEM2 (2 * A_IMG_BYTES + 2 * B2_IMG_BYTES)   // 87040  -> 2 CTAs/SM

extern "C" void kernel_launch(void* const* d_in, const int* in_sizes, int n_in,
                              void* d_out, int out_size)
{
    const float* x     = (const float*)d_in[0];
    const int*   ei    = (const int*)d_in[1];
    const int*   et    = (const int*)d_in[2];
    const float* W1    = (const float*)d_in[3];
    const float* root1 = (const float*)d_in[4];
    const float* b1    = (const float*)d_in[5];
    const float* W2    = (const float*)d_in[6];
    const float* root2 = (const float*)d_in[7];
    const float* b2    = (const float*)d_in[8];
    float* out = (float*)d_out;

    cudaFuncSetAttribute(gemm_fused<128,0>, cudaFuncAttributeMaxDynamicSharedMemorySize, SMEM1);
    cudaFuncSetAttribute(gemm_fused<96,1>,  cudaFuncAttributeMaxDynamicSharedMemorySize, SMEM2);

    // counters are zero on entry (module-load init first call; tail_zero after).
    count_prep<<<(N_EDGES + 255) / 256, 256>>>(ei, et, W1, root1, W2, root2);  // #1
    alloc_base_kernel<<<(N_NODES + 255) / 256, 256>>>();                       // #2
    reorder_kernel<<<(N_EDGES + 255) / 256, 256>>>(ei, et);                    // #3
    gemm_fused<128,0><<<N_TILES64, 512, SMEM1>>>(x, b1, nullptr);              // #4 (profiled)
    gemm_fused<96,1><<<N_TILES64, 512, SMEM2>>>(nullptr, b2, out);             // #5
    tail_zero<<<(N_NODES * N_REL + 255) / 256, 256>>>();                       // #6
}